// round 1
// baseline (speedup 1.0000x reference)
#include <cuda_runtime.h>

#define NW      10
#define DIM     1024
#define THREADS 128
#define EPP     8   // amplitudes per thread (1024/128)

// Gate coefficient scratch (computed each launch by qsa_prep — deterministic).
__device__ float d_g1[NW][8];  // fused RY(ry0)*RX(rx0): a,b,c,d complex (re,im)
__device__ float d_g2[NW][2];  // RY(ry1): cos, sin

__global__ void qsa_prep(const float* __restrict__ rx0,
                         const float* __restrict__ ry0,
                         const float* __restrict__ ry1) {
    int j = threadIdx.x;
    if (j < NW) {
        float c1, s1, c2, s2, c3, s3;
        sincosf(0.5f * rx0[j], &s1, &c1);
        sincosf(0.5f * ry0[j], &s2, &c2);
        sincosf(0.5f * ry1[j], &s3, &c3);
        // G = RY(ry0) @ RX(rx0)
        // a = c1c2 + i s1s2 ; b = -s2c1 - i s1c2 ; c = s2c1 - i s1c2 ; d = c1c2 - i s1s2
        d_g1[j][0] =  c1 * c2;  d_g1[j][1] =  s1 * s2;
        d_g1[j][2] = -s2 * c1;  d_g1[j][3] = -s1 * c2;
        d_g1[j][4] =  s2 * c1;  d_g1[j][5] = -s1 * c2;
        d_g1[j][6] =  c1 * c2;  d_g1[j][7] = -s1 * s2;
        d_g2[j][0] = c3;        d_g2[j][1] = s3;
    }
}

__global__ __launch_bounds__(THREADS)
void qsa_main(const float* __restrict__ x, float* __restrict__ out) {
    __shared__ float2 psi[DIM];
    __shared__ float  sg1[NW * 8];
    __shared__ float  sg2[NW * 2];
    __shared__ float  swred[4 * NW];
    __shared__ float  s_inv2;

    const int t   = threadIdx.x;
    const int row = blockIdx.x;

    if (t < NW * 8) sg1[t] = ((const float*)d_g1)[t];
    if (t < NW * 2) sg2[t] = ((const float*)d_g2)[t];

    // Load row (unnormalized), accumulate sum of squares.
    const float4* xv = (const float4*)(x + (size_t)row * DIM);
    float ss = 0.f;
#pragma unroll
    for (int k = 0; k < 2; k++) {
        float4 v = xv[t + THREADS * k];
        int base = 4 * (t + THREADS * k);
        psi[base + 0] = make_float2(v.x, 0.f);
        psi[base + 1] = make_float2(v.y, 0.f);
        psi[base + 2] = make_float2(v.z, 0.f);
        psi[base + 3] = make_float2(v.w, 0.f);
        ss += v.x * v.x + v.y * v.y + v.z * v.z + v.w * v.w;
    }
#pragma unroll
    for (int o = 16; o; o >>= 1) ss += __shfl_xor_sync(0xffffffffu, ss, o);
    if ((t & 31) == 0) swred[t >> 5] = ss;
    __syncthreads();
    if (t == 0) {
        float s = swred[0] + swred[1] + swred[2] + swred[3];
        s_inv2 = 1.f / fmaxf(s, 1e-24f);   // == 1/max(norm,1e-12)^2
    }

    // ---- Layer 1: fused RY*RX complex 2x2 on each wire (qubit q -> bit 9-q) ----
#pragma unroll
    for (int q = 0; q < NW; q++) {
        const int b = 9 - q;
        const float ar = sg1[8*q+0], ai = sg1[8*q+1], br = sg1[8*q+2], bi = sg1[8*q+3];
        const float cr = sg1[8*q+4], ci = sg1[8*q+5], dr = sg1[8*q+6], di = sg1[8*q+7];
#pragma unroll
        for (int k = 0; k < 4; k++) {
            int p  = t + THREADS * k;
            int i0 = ((p >> b) << (b + 1)) | (p & ((1 << b) - 1));
            int i1 = i0 | (1 << b);
            float2 u = psi[i0], v = psi[i1];
            float2 nu, nv;
            nu.x = ar * u.x - ai * u.y + br * v.x - bi * v.y;
            nu.y = ar * u.y + ai * u.x + br * v.y + bi * v.x;
            nv.x = cr * u.x - ci * u.y + dr * v.x - di * v.y;
            nv.y = cr * u.y + ci * u.x + dr * v.y + di * v.x;
            psi[i0] = nu; psi[i1] = nv;
        }
        __syncthreads();
    }

    // ---- CNOT ring == fixed basis permutation (suffix-XOR map), in-place ----
    // f(i): bits 0..8 -> suffix XOR of bits k..9; bit 9 -> XOR of bits 0..8.
    {
        float2 vals[EPP];
        int    dst[EPP];
#pragma unroll
        for (int k = 0; k < EPP; k++) {
            int i = t + THREADS * k;
            vals[k] = psi[i];
            unsigned y = (unsigned)i;
            y ^= y >> 1; y ^= y >> 2; y ^= y >> 4; y ^= y >> 8;
            dst[k] = (int)((y & 0x1FFu) | (((y ^ ((unsigned)i >> 9)) & 1u) << 9));
        }
        __syncthreads();
#pragma unroll
        for (int k = 0; k < EPP; k++) psi[dst[k]] = vals[k];
        __syncthreads();
    }

    // ---- Layer 2: real RY on each wire ----
#pragma unroll
    for (int q = 0; q < NW; q++) {
        const int b = 9 - q;
        const float c = sg2[2*q+0], s = sg2[2*q+1];
#pragma unroll
        for (int k = 0; k < 4; k++) {
            int p  = t + THREADS * k;
            int i0 = ((p >> b) << (b + 1)) | (p & ((1 << b) - 1));
            int i1 = i0 | (1 << b);
            float2 u = psi[i0], v = psi[i1];
            float2 nu = make_float2(c * u.x - s * v.x, c * u.y - s * v.y);
            float2 nv = make_float2(s * u.x + c * v.x, s * u.y + c * v.y);
            psi[i0] = nu; psi[i1] = nv;
        }
        __syncthreads();
    }

    // ---- <Z_j> = sum_i |psi_i|^2 * (1 - 2*bit_{9-j}(i)), scaled by 1/||x||^2 ----
    float acc[NW];
#pragma unroll
    for (int j = 0; j < NW; j++) acc[j] = 0.f;
#pragma unroll
    for (int k = 0; k < EPP; k++) {
        int i = t + THREADS * k;
        float2 a = psi[i];
        float p = a.x * a.x + a.y * a.y;
#pragma unroll
        for (int j = 0; j < NW; j++)
            acc[j] += ((i >> (9 - j)) & 1) ? -p : p;
    }
#pragma unroll
    for (int o = 16; o; o >>= 1) {
#pragma unroll
        for (int j = 0; j < NW; j++)
            acc[j] += __shfl_xor_sync(0xffffffffu, acc[j], o);
    }
    if ((t & 31) == 0) {
        int w = t >> 5;
#pragma unroll
        for (int j = 0; j < NW; j++) swred[w * NW + j] = acc[j];
    }
    __syncthreads();
    if (t < NW) {
        float e = swred[t] + swred[NW + t] + swred[2 * NW + t] + swred[3 * NW + t];
        out[(size_t)row * NW + t] = e * s_inv2;
    }
}

extern "C" void kernel_launch(void* const* d_in, const int* in_sizes, int n_in,
                              void* d_out, int out_size) {
    const float* x   = (const float*)d_in[0];
    const float* rx0 = (const float*)d_in[1];
    const float* ry0 = (const float*)d_in[2];
    const float* ry1 = (const float*)d_in[3];
    float* out = (float*)d_out;

    int nrows = in_sizes[0] / DIM;  // 4096

    qsa_prep<<<1, 32>>>(rx0, ry0, ry1);
    qsa_main<<<nrows, THREADS>>>(x, out);
}

// round 2
// speedup vs baseline: 2.0462x; 2.0462x over previous
#include <cuda_runtime.h>

#define NW      10
#define DIM     1024
#define THREADS 128

// Gate coefficients (computed per launch by qsa_prep — deterministic).
__device__ float d_g1[NW][8];  // fused RY(ry0)*RX(rx0): a,b,c,d complex (re,im)
__device__ float d_g2[NW][2];  // RY(ry1): cos, sin

__global__ void qsa_prep(const float* __restrict__ rx0,
                         const float* __restrict__ ry0,
                         const float* __restrict__ ry1) {
    int j = threadIdx.x;
    if (j < NW) {
        float c1, s1, c2, s2, c3, s3;
        sincosf(0.5f * rx0[j], &s1, &c1);
        sincosf(0.5f * ry0[j], &s2, &c2);
        sincosf(0.5f * ry1[j], &s3, &c3);
        d_g1[j][0] =  c1 * c2;  d_g1[j][1] =  s1 * s2;
        d_g1[j][2] = -s2 * c1;  d_g1[j][3] = -s1 * c2;
        d_g1[j][4] =  s2 * c1;  d_g1[j][5] = -s1 * c2;
        d_g1[j][6] =  c1 * c2;  d_g1[j][7] = -s1 * s2;
        d_g2[j][0] = c3;        d_g2[j][1] = s3;
    }
}

// Complex 2x2 gate on register bit kb (pairs r[k], r[k | 1<<kb]).
__device__ __forceinline__ void cgate_reg(float2* r, const float* g, const int kb) {
    const float ar = g[0], ai = g[1], br = g[2], bi = g[3];
    const float cr = g[4], ci = g[5], dr = g[6], di = g[7];
#pragma unroll
    for (int m = 0; m < 8; m++) {
        if ((m >> kb) & 1) continue;
        const int k1 = m | (1 << kb);
        float2 u = r[m], v = r[k1];
        r[m].x  = ar * u.x - ai * u.y + br * v.x - bi * v.y;
        r[m].y  = ar * u.y + ai * u.x + br * v.y + bi * v.x;
        r[k1].x = cr * u.x - ci * u.y + dr * v.x - di * v.y;
        r[k1].y = cr * u.y + ci * u.x + dr * v.y + di * v.x;
    }
}

// Complex 2x2 gate on lane bit lb via warp shuffle.
__device__ __forceinline__ void cgate_shfl(float2* r, const float* g,
                                           const int lb, const int lane) {
    const bool hi = (lane >> lb) & 1;
    const float pr = hi ? g[6] : g[0];
    const float pi = hi ? g[7] : g[1];
    const float qr = hi ? g[4] : g[2];
    const float qi = hi ? g[5] : g[3];
#pragma unroll
    for (int k = 0; k < 8; k++) {
        float vx = __shfl_xor_sync(0xffffffffu, r[k].x, 1 << lb);
        float vy = __shfl_xor_sync(0xffffffffu, r[k].y, 1 << lb);
        float ux = r[k].x, uy = r[k].y;
        r[k].x = pr * ux - pi * uy + qr * vx - qi * vy;
        r[k].y = pr * uy + pi * ux + qr * vy + qi * vx;
    }
}

// Real RY gate [[c,-s],[s,c]] on register bit kb.
__device__ __forceinline__ void rgate_reg(float2* r, const float* g, const int kb) {
    const float c = g[0], s = g[1];
#pragma unroll
    for (int m = 0; m < 8; m++) {
        if ((m >> kb) & 1) continue;
        const int k1 = m | (1 << kb);
        float2 u = r[m], v = r[k1];
        r[m]  = make_float2(c * u.x - s * v.x, c * u.y - s * v.y);
        r[k1] = make_float2(s * u.x + c * v.x, s * u.y + c * v.y);
    }
}

// Real RY gate on lane bit lb via warp shuffle.
__device__ __forceinline__ void rgate_shfl(float2* r, const float* g,
                                           const int lb, const int lane) {
    const bool hi = (lane >> lb) & 1;
    const float p = g[0];                       // c either way
    const float q = hi ? g[1] : -g[1];          // +s / -s
#pragma unroll
    for (int k = 0; k < 8; k++) {
        float vx = __shfl_xor_sync(0xffffffffu, r[k].x, 1 << lb);
        float vy = __shfl_xor_sync(0xffffffffu, r[k].y, 1 << lb);
        r[k].x = p * r[k].x + q * vx;
        r[k].y = p * r[k].y + q * vy;
    }
}

__global__ __launch_bounds__(THREADS)
void qsa_main(const float* __restrict__ x, float* __restrict__ out) {
    __shared__ float2 buf0[DIM];
    __shared__ float2 buf1[DIM];
    __shared__ float  sg1[NW * 8];
    __shared__ float  sg2[NW * 2];
    __shared__ float  swred[4 * NW];
    __shared__ float  s_inv2;

    const int t    = threadIdx.x;
    const int lane = t & 31;
    const int w    = t >> 5;
    const int row  = blockIdx.x;

    if (t < NW * 8) sg1[t] = ((const float*)d_g1)[t];
    if (t < NW * 2) sg2[t] = ((const float*)d_g2)[t];

    // ---- Load (layout A: i = t + 128k; lane=bits0-4, warp=bits5-6, k=bits7-9) ----
    float2 r[8];
    float ss = 0.f;
    const float* xr = x + (size_t)row * DIM;
#pragma unroll
    for (int k = 0; k < 8; k++) {
        float v = __ldg(xr + t + THREADS * k);
        r[k] = make_float2(v, 0.f);
        ss += v * v;
    }
#pragma unroll
    for (int o = 16; o; o >>= 1) ss += __shfl_xor_sync(0xffffffffu, ss, o);
    if (lane == 0) swred[w] = ss;
    __syncthreads();                                   // sync0 (also covers sg preload)
    if (t == 0) {
        float s = swred[0] + swred[1] + swred[2] + swred[3];
        s_inv2 = 1.f / fmaxf(s, 1e-24f);               // == 1/max(norm,1e-12)^2
    }

    // ======== Layer 1 (fused complex RY*RX per wire) ========
    // Register bits: kb=2 -> bit9 -> q0; kb=1 -> bit8 -> q1; kb=0 -> bit7 -> q2.
    cgate_reg(r, sg1 + 8 * 0, 2);
    cgate_reg(r, sg1 + 8 * 1, 1);
    cgate_reg(r, sg1 + 8 * 2, 0);
    // Lane bits: lb -> bit lb -> qubit 9-lb.
    cgate_shfl(r, sg1 + 8 * 5, 4, lane);
    cgate_shfl(r, sg1 + 8 * 6, 3, lane);
    cgate_shfl(r, sg1 + 8 * 7, 2, lane);
    cgate_shfl(r, sg1 + 8 * 8, 1, lane);
    cgate_shfl(r, sg1 + 8 * 9, 0, lane);

    // ---- Exchange A -> B (layout B: i = lane | (k<<5) | (w<<8)) ----
#pragma unroll
    for (int k = 0; k < 8; k++) buf0[t + THREADS * k] = r[k];
    __syncthreads();                                   // sync1
#pragma unroll
    for (int k = 0; k < 8; k++) r[k] = buf0[lane | (k << 5) | (w << 8)];

    // Layout B register bits: kb=0 -> bit5 -> q4; kb=1 -> bit6 -> q3.
    cgate_reg(r, sg1 + 8 * 4, 0);
    cgate_reg(r, sg1 + 8 * 3, 1);

    // ---- CNOT ring (fixed permutation), fused with exchange B -> A ----
#pragma unroll
    for (int k = 0; k < 8; k++) {
        unsigned i = (unsigned)(lane | (k << 5) | (w << 8));
        unsigned y = i;
        y ^= y >> 1; y ^= y >> 2; y ^= y >> 4; y ^= y >> 8;
        unsigned dst = (y & 0x1FFu) | (((y ^ (i >> 9)) & 1u) << 9);
        buf1[dst] = r[k];
    }
    __syncthreads();                                   // sync2
#pragma unroll
    for (int k = 0; k < 8; k++) r[k] = buf1[t + THREADS * k];

    // ======== Layer 2 (real RY per wire) ========
    rgate_reg(r, sg2 + 2 * 0, 2);
    rgate_reg(r, sg2 + 2 * 1, 1);
    rgate_reg(r, sg2 + 2 * 2, 0);
    rgate_shfl(r, sg2 + 2 * 5, 4, lane);
    rgate_shfl(r, sg2 + 2 * 6, 3, lane);
    rgate_shfl(r, sg2 + 2 * 7, 2, lane);
    rgate_shfl(r, sg2 + 2 * 8, 1, lane);
    rgate_shfl(r, sg2 + 2 * 9, 0, lane);

    // ---- Exchange A -> B again (safe: buf0's prior reads fenced by sync2) ----
#pragma unroll
    for (int k = 0; k < 8; k++) buf0[t + THREADS * k] = r[k];
    __syncthreads();                                   // sync3
#pragma unroll
    for (int k = 0; k < 8; k++) r[k] = buf0[lane | (k << 5) | (w << 8)];

    rgate_reg(r, sg2 + 2 * 4, 0);
    rgate_reg(r, sg2 + 2 * 3, 1);

    // ======== <Z_j> reduction (layout B: bits 5,6,7 = k; 8,9 = w; 0-4 = lane) ====
    float tot = 0.f, a2 = 0.f, a3 = 0.f, a4 = 0.f;   // q2<->bit7(k2), q3<->bit6(k1), q4<->bit5(k0)
#pragma unroll
    for (int k = 0; k < 8; k++) {
        float p = r[k].x * r[k].x + r[k].y * r[k].y;
        tot += p;
        a4 += (k & 1) ? -p : p;
        a3 += (k & 2) ? -p : p;
        a2 += (k & 4) ? -p : p;
    }
    // 9 warp reductions: tot, (lane-signed tot) x5 for q5..q9, a2,a3,a4
    float vals[9];
    vals[0] = tot;
    vals[1] = ((lane >> 4) & 1) ? -tot : tot;   // q5 (bit4)
    vals[2] = ((lane >> 3) & 1) ? -tot : tot;   // q6
    vals[3] = ((lane >> 2) & 1) ? -tot : tot;   // q7
    vals[4] = ((lane >> 1) & 1) ? -tot : tot;   // q8
    vals[5] = ( lane       & 1) ? -tot : tot;   // q9
    vals[6] = a2; vals[7] = a3; vals[8] = a4;
#pragma unroll
    for (int o = 16; o; o >>= 1) {
#pragma unroll
        for (int j = 0; j < 9; j++)
            vals[j] += __shfl_xor_sync(0xffffffffu, vals[j], o);
    }
    if (lane == 0) {
        // q0 <-> bit9 = w>>1 ; q1 <-> bit8 = w&1 (uniform per warp; sign from tot)
        swred[w * NW + 0] = ((w >> 1) & 1) ? -vals[0] : vals[0];
        swred[w * NW + 1] = ( w       & 1) ? -vals[0] : vals[0];
        swred[w * NW + 2] = vals[6];
        swred[w * NW + 3] = vals[7];
        swred[w * NW + 4] = vals[8];
        swred[w * NW + 5] = vals[1];
        swred[w * NW + 6] = vals[2];
        swred[w * NW + 7] = vals[3];
        swred[w * NW + 8] = vals[4];
        swred[w * NW + 9] = vals[5];
    }
    __syncthreads();                                   // sync4
    if (t < NW) {
        float e = swred[t] + swred[NW + t] + swred[2 * NW + t] + swred[3 * NW + t];
        out[(size_t)row * NW + t] = e * s_inv2;
    }
}

extern "C" void kernel_launch(void* const* d_in, const int* in_sizes, int n_in,
                              void* d_out, int out_size) {
    const float* x   = (const float*)d_in[0];
    const float* rx0 = (const float*)d_in[1];
    const float* ry0 = (const float*)d_in[2];
    const float* ry1 = (const float*)d_in[3];
    float* out = (float*)d_out;

    int nrows = in_sizes[0] / DIM;  // 4096

    qsa_prep<<<1, 32>>>(rx0, ry0, ry1);
    qsa_main<<<nrows, THREADS>>>(x, out);
}